// round 9
// baseline (speedup 1.0000x reference)
#include <cuda_runtime.h>

// self_attention_76416058130984 — GB300 sm_103a
// frames: [4, B=8, C=64, H=160, W=160] fp32 -> out: [8, 256, 160, 160] fp32
//
// Per pixel: E_ij(c) = exp(x_i[c]*x_j[c]) (symmetric, 10 unique per channel),
// denom_i = sum_{j,c} E_ij(c),  out_i[c] = (sum_j E_ij(c)*x_j[c]) / denom_i.
// No max-subtraction needed (logits bounded ~40, fp32 safe; softmax shift-invariant).
//
// R8 = R7 resubmit (R8 bench was an infra failure, kernel never ran):
// 128-thread blocks / 16-pixel tiles -> 9 blocks/SM for phase interleaving
// (R4 showed the reg-cap route kills load MLP; registers stay uncapped here).
// Reduction: 15 SHFL + 1 RCP per pixel instead of 20 + 4.

#define B_   8
#define C_   64
#define H_   160
#define W_   160
#define HW_  (H_*W_)      // 25600
#define WTILE 16
#define NTHREADS 128
#define SPAD 17           // odd -> conflict-free transposed (column) access

__device__ __forceinline__ float ex2a(float x) {
    float y; asm("ex2.approx.f32 %0, %1;" : "=f"(y) : "f"(x)); return y;
}
__device__ __forceinline__ float rcpa(float x) {
    float y; asm("rcp.approx.f32 %0, %1;" : "=f"(y) : "f"(x)); return y;
}

// 10 unique exps -> row sums r[i] and gated sums y[i]
__device__ __forceinline__ void attn4(const float a[4], float y[4], float r[4]) {
    const float L2E = 1.44269504f;   // log2(e)
    float b0 = a[0]*L2E, b1 = a[1]*L2E, b2 = a[2]*L2E, b3 = a[3]*L2E;
    float e00 = ex2a(a[0]*b0), e01 = ex2a(a[0]*b1), e02 = ex2a(a[0]*b2), e03 = ex2a(a[0]*b3);
    float e11 = ex2a(a[1]*b1), e12 = ex2a(a[1]*b2), e13 = ex2a(a[1]*b3);
    float e22 = ex2a(a[2]*b2), e23 = ex2a(a[2]*b3);
    float e33 = ex2a(a[3]*b3);
    r[0] = (e00+e01)+(e02+e03);
    r[1] = (e01+e11)+(e12+e13);
    r[2] = (e02+e12)+(e22+e23);
    r[3] = (e03+e13)+(e23+e33);
    y[0] = fmaf(e00,a[0], fmaf(e01,a[1], fmaf(e02,a[2], e03*a[3])));
    y[1] = fmaf(e01,a[0], fmaf(e11,a[1], fmaf(e12,a[2], e13*a[3])));
    y[2] = fmaf(e02,a[0], fmaf(e12,a[1], fmaf(e22,a[2], e23*a[3])));
    y[3] = fmaf(e03,a[0], fmaf(e13,a[1], fmaf(e23,a[2], e33*a[3])));
}

__global__ void __launch_bounds__(NTHREADS)
self_attn_fused_kernel(const float* __restrict__ frames, float* __restrict__ out)
{
    // one buffer, reused in place for outputs: [256 rows][SPAD]
    __shared__ float s[4*C_*SPAD];

    const int t    = threadIdx.x;
    const int bidx = blockIdx.x;          // B_*H_*(W_/WTILE) = 12800 blocks
    const int tile = bidx % (W_/WTILE);
    const int h    = (bidx / (W_/WTILE)) % H_;
    const int b    = bidx / ((W_/WTILE)*H_);
    const int w0   = tile * WTILE;
    const int sp_in = h*W_ + w0;

    // Per-thread row/quad decomposition shared by Phase 1 and Phase 3:
    // thread handles float4 #q of rows {row0 + 32*it}, it=0..7.
    const int row0 = t >> 2;              // 0..31
    const int q4   = (t & 3) * 4;         // 0,4,8,12

    // ---- Phase 1: coalesced load, 256 rows x 16 floats (4 x float4 per row)
    #pragma unroll
    for (int it = 0; it < 8; ++it) {
        const int row = row0 + it*32;     // j*64 + c
        const int j   = row >> 6;
        const int c   = row & 63;
        const float4 v = *reinterpret_cast<const float4*>(
            frames + ((j*B_ + b)*C_ + c)*HW_ + sp_in + q4);
        float* sp = s + row*SPAD + q4;
        sp[0] = v.x; sp[1] = v.y; sp[2] = v.z; sp[3] = v.w;
    }
    __syncthreads();

    // ---- Phase 2: each warp owns 4 pixels; lanes = channels (2 per lane)
    const int warp = t >> 5, lane = t & 31;
    #pragma unroll
    for (int pi = 0; pi < 4; ++pi) {
        const int p = warp*4 + pi;
        float a0[4], a1[4];
        #pragma unroll
        for (int j = 0; j < 4; ++j) {
            a0[j] = s[(j*C_ + lane     )*SPAD + p];
            a1[j] = s[(j*C_ + lane + 32)*SPAD + p];
        }
        float y0[4], y1[4], r0[4], r1[4];
        attn4(a0, y0, r0);
        attn4(a1, y1, r1);
        float d[4];
        #pragma unroll
        for (int i = 0; i < 4; ++i) d[i] = r0[i] + r1[i];

        // Reduction, cheap form:
        // (a) sum all 4 d's within groups of 4 lanes (bits 0,1): 8 SHFL
        #pragma unroll
        for (int m = 1; m <= 2; m <<= 1) {
            #pragma unroll
            for (int i = 0; i < 4; ++i)
                d[i] += __shfl_xor_sync(0xffffffffu, d[i], m);
        }
        // (b) each lane takes the d of its class (lane&3), sums across the
        //     8 groups (bits 2,3,4): 3 SHFL -> full denominator D[lane&3]
        const int cls = lane & 3;
        float v = cls == 0 ? d[0] : (cls == 1 ? d[1] : (cls == 2 ? d[2] : d[3]));
        #pragma unroll
        for (int m = 4; m <= 16; m <<= 1)
            v += __shfl_xor_sync(0xffffffffu, v, m);
        // (c) one reciprocal, then broadcast the 4 inverses within each group
        const float inv = rcpa(v);
        const int base = lane & ~3;
        float invD[4];
        #pragma unroll
        for (int i = 0; i < 4; ++i)
            invD[i] = __shfl_sync(0xffffffffu, inv, base + i);

        // shfl chain above also guarantees all lanes finished reading this
        // pixel's column before we overwrite it in place.
        #pragma unroll
        for (int i = 0; i < 4; ++i) {
            s[(i*C_ + lane     )*SPAD + p] = y0[i] * invD[i];
            s[(i*C_ + lane + 32)*SPAD + p] = y1[i] * invD[i];
        }
    }
    __syncthreads();

    // ---- Phase 3: coalesced store, out[b][row][h][w0..w0+15], row = i*64+c
    const int out_base = (b*4*C_)*HW_ + sp_in;
    #pragma unroll
    for (int it = 0; it < 8; ++it) {
        const int row = row0 + it*32;
        const float* sp = s + row*SPAD + q4;
        float4 v = make_float4(sp[0], sp[1], sp[2], sp[3]);
        *reinterpret_cast<float4*>(out + out_base + row*HW_ + q4) = v;
    }
}

extern "C" void kernel_launch(void* const* d_in, const int* in_sizes, int n_in,
                              void* d_out, int out_size)
{
    const float* frames = (const float*)d_in[0];
    float* out = (float*)d_out;
    const int nblocks = B_ * H_ * (W_/WTILE);   // 12800
    self_attn_fused_kernel<<<nblocks, NTHREADS>>>(frames, out);
}

// round 11
// speedup vs baseline: 1.5552x; 1.5552x over previous
#include <cuda_runtime.h>
#include <cstdint>

// self_attention_76416058130984 — GB300 sm_103a
// frames: [4, B=8, C=64, H=160, W=160] fp32 -> out: [8, 256, 160, 160] fp32
//
// Per pixel: E_ij(c) = exp(x_i[c]*x_j[c]) (symmetric, 10 unique per channel),
// denom_i = sum_{j,c} E_ij(c),  out_i[c] = (sum_j E_ij(c)*x_j[c]) / denom_i.
// No max-subtraction needed (logits bounded ~40, fp32 safe; softmax shift-invariant).
//
// R11 = R10 resubmit (R10 bench was an infra failure, kernel never ran):
// (a) cp.async double-buffered tile prefetch (4 tiles/block) — memory in
// flight during compute by construction, no reliance on inter-block phasing
// (R0/R4/R9 showed perf tracks load batching, not occupancy).
// (b) lane=pixel / warp=channel-slice mapping: zero SHFLs, local denominator
// accumulation, unnormalized y written in place (disjoint rows per warp),
// tiny pd[] block reduction, normalization folded into the store phase.
// All SMEM accesses lane-consecutive -> no padding -> cp.async-compatible.

#define B_       8
#define C_       64
#define H_       160
#define W_       160
#define HW_      (H_*W_)            // 25600
#define WTILE    32
#define NTHREADS 256
#define TPB      4                  // tiles per block
#define NTILES   (B_*H_*(W_/WTILE)) // 6400
#define TILE_F   (4*C_*WTILE)       // 8192 floats = 32KB
#define PD_OFF   (2*TILE_F)         // pd[8 warps][4 i][32 px] = 1024 floats
#define INVD_OFF (PD_OFF + 8*4*32)  // invd[4 i][32 px] = 128 floats
#define SMEM_F   (INVD_OFF + 4*32)  // 17664 floats
#define SMEM_BYTES (SMEM_F*4)       // 70656 B -> 3 blocks/SM

__device__ __forceinline__ float ex2a(float x) {
    float y; asm("ex2.approx.f32 %0, %1;" : "=f"(y) : "f"(x)); return y;
}
__device__ __forceinline__ float rcpa(float x) {
    float y; asm("rcp.approx.f32 %0, %1;" : "=f"(y) : "f"(x)); return y;
}
__device__ __forceinline__ void cpasync16(uint32_t dst_s, const void* src_g) {
    asm volatile("cp.async.cg.shared.global [%0], [%1], 16;"
                 :: "r"(dst_s), "l"(src_g));
}

// 10 unique exps -> row sums r[i] and gated sums y[i]
__device__ __forceinline__ void attn4(const float a[4], float y[4], float r[4]) {
    const float L2E = 1.44269504f;   // log2(e)
    float b0 = a[0]*L2E, b1 = a[1]*L2E, b2 = a[2]*L2E, b3 = a[3]*L2E;
    float e00 = ex2a(a[0]*b0), e01 = ex2a(a[0]*b1), e02 = ex2a(a[0]*b2), e03 = ex2a(a[0]*b3);
    float e11 = ex2a(a[1]*b1), e12 = ex2a(a[1]*b2), e13 = ex2a(a[1]*b3);
    float e22 = ex2a(a[2]*b2), e23 = ex2a(a[2]*b3);
    float e33 = ex2a(a[3]*b3);
    r[0] = (e00+e01)+(e02+e03);
    r[1] = (e01+e11)+(e12+e13);
    r[2] = (e02+e12)+(e22+e23);
    r[3] = (e03+e13)+(e23+e33);
    y[0] = fmaf(e00,a[0], fmaf(e01,a[1], fmaf(e02,a[2], e03*a[3])));
    y[1] = fmaf(e01,a[0], fmaf(e11,a[1], fmaf(e12,a[2], e13*a[3])));
    y[2] = fmaf(e02,a[0], fmaf(e12,a[1], fmaf(e22,a[2], e23*a[3])));
    y[3] = fmaf(e03,a[0], fmaf(e13,a[1], fmaf(e23,a[2], e33*a[3])));
}

// async-copy one 32-pixel tile (256 rows x 32 floats) into smem buffer
__device__ __forceinline__ void ca_tile(uint32_t dst_s, int tid, int t,
                                        const float* __restrict__ frames) {
    const int tl = tid % (W_/WTILE);
    const int h  = (tid / (W_/WTILE)) % H_;
    const int b  = tid / ((W_/WTILE)*H_);
    const int sp = h*W_ + tl*WTILE;
    #pragma unroll
    for (int m = 0; m < 8; ++m) {
        const int f   = m*NTHREADS + t;   // 0..2047 quad index
        const int row = f >> 3;           // j*64 + c
        const int q   = f & 7;
        const int j   = row >> 6;
        const int c   = row & 63;
        cpasync16(dst_s + (uint32_t)(row*WTILE + q*4)*4u,
                  frames + ((j*B_ + b)*C_ + c)*HW_ + sp + q*4);
    }
}

__global__ void __launch_bounds__(NTHREADS)
self_attn_fused_kernel(const float* __restrict__ frames, float* __restrict__ out)
{
    extern __shared__ float s[];
    const uint32_t s_u32 = (uint32_t)__cvta_generic_to_shared(s);
    const int t    = threadIdx.x;
    const int warp = t >> 5, lane = t & 31;
    const int first = blockIdx.x * TPB;

    // prologue: prefetch tile 0
    ca_tile(s_u32, first, t, frames);
    asm volatile("cp.async.commit_group;");

    for (int k = 0; k < TPB; ++k) {
        float* buf = s + (k & 1)*TILE_F;

        // prefetch tile k+1 into the other buffer, then wait for tile k
        if (k + 1 < TPB) {
            ca_tile(s_u32 + (uint32_t)(((k+1)&1)*TILE_F)*4u, first+k+1, t, frames);
            asm volatile("cp.async.commit_group;");
            asm volatile("cp.async.wait_group 1;");
        } else {
            asm volatile("cp.async.wait_group 0;");
        }
        __syncthreads();

        // ---- Phase 2a: lane = pixel, warp owns channels [8w, 8w+8)
        // accumulate local partial denominators; write unnormalized y in place
        // (warp w touches only rows {*64 + c : c in its slice} -> disjoint)
        float d[4] = {0.f, 0.f, 0.f, 0.f};
        #pragma unroll
        for (int cc = 0; cc < 8; ++cc) {
            const int c = warp*8 + cc;
            float a[4];
            #pragma unroll
            for (int j = 0; j < 4; ++j)
                a[j] = buf[(j*C_ + c)*WTILE + lane];
            float y[4], r[4];
            attn4(a, y, r);
            #pragma unroll
            for (int i = 0; i < 4; ++i) {
                d[i] += r[i];
                buf[(i*C_ + c)*WTILE + lane] = y[i];
            }
        }
        #pragma unroll
        for (int i = 0; i < 4; ++i)
            s[PD_OFF + (warp*4 + i)*32 + lane] = d[i];
        __syncthreads();

        // ---- Phase 2b: reduce partial denoms across 8 warps, one rcp each
        if (t < 128) {
            const int i = t >> 5, p = t & 31;
            float sum = 0.f;
            #pragma unroll
            for (int w = 0; w < 8; ++w)
                sum += s[PD_OFF + (w*4 + i)*32 + p];
            s[INVD_OFF + i*32 + p] = rcpa(sum);
        }
        __syncthreads();

        // ---- Phase 3: normalize + coalesced store
        {
            const int tid = first + k;
            const int tl = tid % (W_/WTILE);
            const int h  = (tid / (W_/WTILE)) % H_;
            const int b  = tid / ((W_/WTILE)*H_);
            const int sp = h*W_ + tl*WTILE;
            const int row0 = t >> 3;          // 0..31
            const int q4   = (t & 7)*4;       // 0..28
            #pragma unroll
            for (int it = 0; it < 8; ++it) {
                const int row = row0 + it*32; // i*64 + c
                const int i   = row >> 6;
                const float4 iv = *reinterpret_cast<const float4*>(
                    s + INVD_OFF + i*32 + q4);
                const float* yp = buf + row*WTILE + q4;
                float4 v = make_float4(yp[0]*iv.x, yp[1]*iv.y,
                                       yp[2]*iv.z, yp[3]*iv.w);
                *reinterpret_cast<float4*>(
                    out + (b*4*C_ + row)*HW_ + sp + q4) = v;
            }
        }
        __syncthreads();   // protect buf/pd/invd reuse vs next iteration's cp.async
    }
}

extern "C" void kernel_launch(void* const* d_in, const int* in_sizes, int n_in,
                              void* d_out, int out_size)
{
    const float* frames = (const float*)d_in[0];
    float* out = (float*)d_out;
    cudaFuncSetAttribute(self_attn_fused_kernel,
                         cudaFuncAttributeMaxDynamicSharedMemorySize, SMEM_BYTES);
    self_attn_fused_kernel<<<NTILES/TPB, NTHREADS, SMEM_BYTES>>>(frames, out);
}